// round 3
// baseline (speedup 1.0000x reference)
#include <cuda_runtime.h>
#include <cstdint>
#include <math.h>

// Problem constants
#define BATCH   131072
#define DIM     256
#define KTOT    1024      // 3*256 (z concat) + 256 (noise_z, 0.1 folded)
#define NOUT    32        // 16 route logits + 16 noise pre-softplus
#define KSEL    4

// Tiling
#define RPB     256       // rows per block
#define KC      32        // K-chunk per stage
#define SMS     36        // padded input row stride (floats)
#define WSTR    36        // padded weight row stride (floats)
#define NCHUNK  (KTOT / KC)

// Combined weights, built on-device each call
__device__ float g_wT2[NOUT * KTOT];   // [o][k] layout
__device__ float g_biasC[NOUT];

// ---------------------------------------------------------------------------
__device__ __forceinline__ void cpa16(void* s, const void* g) {
    unsigned sa = (unsigned)__cvta_generic_to_shared(s);
    asm volatile("cp.async.cg.shared.global [%0], [%1], 16;\n" :: "r"(sa), "l"(g));
}
#define CP_COMMIT() asm volatile("cp.async.commit_group;\n" ::: "memory")
#define CP_WAIT1()  asm volatile("cp.async.wait_group 1;\n"  ::: "memory")

#define FMA2(acc, a, b) \
    asm("fma.rn.f32x2 %0, %1, %2, %0;" : "+l"(acc) : "l"(a), "l"(b))

__device__ __forceinline__ float fold2(unsigned long long v) {
    float lo, hi;
    asm("mov.b64 {%0,%1}, %2;" : "=f"(lo), "=f"(hi) : "l"(v));
    return lo + hi;
}

// ---------------------------------------------------------------------------
// Pre-kernel: combined weights in fp64 with 4-way ILP
// ---------------------------------------------------------------------------
__global__ void build_combined(const float* __restrict__ W_proj,
                               const float* __restrict__ b_proj,
                               const float* __restrict__ W_route,
                               const float* __restrict__ b_route,
                               const float* __restrict__ W_noise,
                               const float* __restrict__ b_noise) {
    int idx = blockIdx.x * blockDim.x + threadIdx.x;
    if (idx >= KTOT * NOUT) return;
    int o = idx & 31;
    int k = idx >> 5;
    int p = o & 15;
    const float* Wsel = (o < 16) ? W_route : W_noise;

    float val;
    if (k < 768) {
        double a0 = 0.0, a1 = 0.0, a2 = 0.0, a3 = 0.0;
        #pragma unroll 4
        for (int d = 0; d < 256; d += 4) {
            a0 += (double)Wsel[p * 256 + d + 0] * (double)W_proj[(d + 0) * 768 + k];
            a1 += (double)Wsel[p * 256 + d + 1] * (double)W_proj[(d + 1) * 768 + k];
            a2 += (double)Wsel[p * 256 + d + 2] * (double)W_proj[(d + 2) * 768 + k];
            a3 += (double)Wsel[p * 256 + d + 3] * (double)W_proj[(d + 3) * 768 + k];
        }
        val = (float)((a0 + a1) + (a2 + a3));
    } else {
        val = 0.1f * Wsel[p * 256 + (k - 768)];
    }
    g_wT2[o * KTOT + k] = val;

    if (idx < 32) {
        double a0 = (o < 16) ? (double)b_route[p] : (double)b_noise[p];
        double a1 = 0.0, a2 = 0.0, a3 = 0.0;
        for (int d = 0; d < 256; d += 4) {
            a0 += (double)Wsel[p * 256 + d + 0] * (double)b_proj[d + 0];
            a1 += (double)Wsel[p * 256 + d + 1] * (double)b_proj[d + 1];
            a2 += (double)Wsel[p * 256 + d + 2] * (double)b_proj[d + 2];
            a3 += (double)Wsel[p * 256 + d + 3] * (double)b_proj[d + 3];
        }
        g_biasC[o] = (float)((a0 + a1) + (a2 + a3));
    }
}

// ---------------------------------------------------------------------------
// Main fused kernel: [256,1024]x[1024,32] per block via FFMA2, cp.async
// double-buffered staging, fused softplus/noise/softmax/top4 epilogue.
// Thread tile: 4 rows (stride 64) x 8 outputs (stride 4).
// ---------------------------------------------------------------------------
__global__ __launch_bounds__(256, 2) void router_main(
    const float* __restrict__ z_n,     const float* __restrict__ z_sea,
    const float* __restrict__ z_trend, const float* __restrict__ noise_z,
    const float* __restrict__ noise_r, const int* __restrict__ patch_cand,
    float* __restrict__ out)
{
    extern __shared__ float smem[];
    // layout: in[2][RPB][SMS] then w[2][NOUT][WSTR]
    float (*in_s)[RPB][SMS]  = (float(*)[RPB][SMS])smem;
    float (*w_s)[NOUT][WSTR] = (float(*)[NOUT][WSTR])(smem + 2 * RPB * SMS);

    const int tid  = threadIdx.x;
    const int row0 = blockIdx.x * RPB;
    const int og   = tid & 3;    // outputs og, og+4, ..., og+28
    const int rg   = tid >> 2;   // rows rg, rg+64, rg+128, rg+192 (block-local)

    // ---- staging helper (inlined logic) ----
    auto stage = [&](int buf, int c) {
        const float* src = (c < 16) ? ((c < 8) ? z_n : z_sea)
                                    : ((c < 24) ? z_trend : noise_z);
        const int koff = (c & 7) * KC;
        #pragma unroll
        for (int i = 0; i < 8; i++) {
            int idx = tid + i * 256;          // 0..2047
            int r   = idx >> 3;
            int seg = idx & 7;
            cpa16(&in_s[buf][r][seg * 4],
                  src + (size_t)(row0 + r) * DIM + koff + seg * 4);
        }
        {
            int o   = tid >> 3;               // 0..31
            int seg = tid & 7;
            cpa16(&w_s[buf][o][seg * 4],
                  g_wT2 + (size_t)o * KTOT + c * KC + seg * 4);
        }
    };

    unsigned long long acc2[4][8];
    #pragma unroll
    for (int r = 0; r < 4; r++)
        #pragma unroll
        for (int o = 0; o < 8; o++) acc2[r][o] = 0ull;

    stage(0, 0);
    CP_COMMIT();

    for (int c = 0; c < NCHUNK; c++) {
        const int cur = c & 1;
        if (c + 1 < NCHUNK) stage(cur ^ 1, c + 1);
        CP_COMMIT();
        CP_WAIT1();
        __syncthreads();

        #pragma unroll
        for (int k = 0; k < KC; k += 4) {
            ulonglong2 a[4];
            #pragma unroll
            for (int rr = 0; rr < 4; rr++)
                a[rr] = *(const ulonglong2*)&in_s[cur][rg + rr * 64][k];
            #pragma unroll
            for (int oo = 0; oo < 8; oo++) {
                ulonglong2 w = *(const ulonglong2*)&w_s[cur][og + oo * 4][k];
                #pragma unroll
                for (int rr = 0; rr < 4; rr++) {
                    FMA2(acc2[rr][oo], a[rr].x, w.x);
                    FMA2(acc2[rr][oo], a[rr].y, w.y);
                }
            }
        }
        __syncthreads();   // protect buffer being re-staged next iteration
    }

    // ---- fold packed accumulators, stash per-row results in smem ----
    float (*res)[33] = (float(*)[33])smem;   // 256 x 33 floats, fits buffer 0
    #pragma unroll
    for (int rr = 0; rr < 4; rr++)
        #pragma unroll
        for (int oo = 0; oo < 8; oo++)
            res[rg + rr * 64][og + oo * 4] = fold2(acc2[rr][oo]);
    __syncthreads();

    // ---- epilogue: one thread per row ----
    {
        const int grow = row0 + tid;
        float v[32];
        #pragma unroll
        for (int o = 0; o < 32; o++) v[o] = res[tid][o];

        float nr[16];
        #pragma unroll
        for (int i = 0; i < 4; i++) {
            float4 t = __ldg((const float4*)(noise_r + (size_t)grow * 16 + i * 4));
            nr[i * 4 + 0] = t.x; nr[i * 4 + 1] = t.y;
            nr[i * 4 + 2] = t.z; nr[i * 4 + 3] = t.w;
        }

        float logit[16];
        #pragma unroll
        for (int p = 0; p < 16; p++) {
            float pre = v[16 + p] + g_biasC[16 + p];
            float sp  = fmaxf(pre, 0.0f) + log1pf(expf(-fabsf(pre)));
            logit[p]  = v[p] + g_biasC[p] + nr[p] * sp;
        }

        float m = logit[0];
        #pragma unroll
        for (int p = 1; p < 16; p++) m = fmaxf(m, logit[p]);
        float e[16], s = 0.0f;
        #pragma unroll
        for (int p = 0; p < 16; p++) { e[p] = expf(logit[p] - m); s += e[p]; }
        float w[16];
        #pragma unroll
        for (int p = 0; p < 16; p++) w[p] = e[p] / s;

        float sp_out[16];
        #pragma unroll
        for (int p = 0; p < 16; p++) sp_out[p] = 0.0f;
        int idxs[4];
        unsigned mask = 0u;
        #pragma unroll
        for (int kk = 0; kk < 4; kk++) {
            float best = -1.0f; int bi = 0;
            #pragma unroll
            for (int p = 0; p < 16; p++) {
                bool free = ((mask >> p) & 1u) == 0u;
                if (free && w[p] > best) { best = w[p]; bi = p; }
            }
            mask |= 1u << bi;
            idxs[kk] = bi;
            sp_out[bi] = best;
        }

        float* sp_ptr = out + (size_t)grow * 16;
        #pragma unroll
        for (int i = 0; i < 4; i++) {
            float4 t = make_float4(sp_out[i * 4 + 0], sp_out[i * 4 + 1],
                                   sp_out[i * 4 + 2], sp_out[i * 4 + 3]);
            *(float4*)(sp_ptr + i * 4) = t;
        }
        float* pp = out + (size_t)BATCH * 16 + (size_t)grow * 4;
        float* ip = out + (size_t)BATCH * 20 + (size_t)grow * 4;
        #pragma unroll
        for (int kk = 0; kk < 4; kk++) {
            pp[kk] = (float)__ldg(patch_cand + idxs[kk]);
            ip[kk] = (float)idxs[kk];
        }
    }
}

// ---------------------------------------------------------------------------
extern "C" void kernel_launch(void* const* d_in, const int* in_sizes, int n_in,
                              void* d_out, int out_size) {
    const float* z_n        = (const float*)d_in[0];
    const float* z_sea      = (const float*)d_in[1];
    const float* z_trend    = (const float*)d_in[2];
    const float* noise_z    = (const float*)d_in[3];
    const float* noise_r    = (const float*)d_in[4];
    const int*   patch_cand = (const int*)  d_in[5];
    const float* W_proj     = (const float*)d_in[6];
    const float* b_proj     = (const float*)d_in[7];
    const float* W_route    = (const float*)d_in[8];
    const float* b_route    = (const float*)d_in[9];
    const float* W_noise    = (const float*)d_in[10];
    const float* b_noise    = (const float*)d_in[11];
    float* out = (float*)d_out;

    const int smem_bytes = (2 * RPB * SMS + 2 * NOUT * WSTR) * sizeof(float);
    static bool attr_set = false;
    if (!attr_set) {
        cudaFuncSetAttribute(router_main,
                             cudaFuncAttributeMaxDynamicSharedMemorySize,
                             smem_bytes);
        attr_set = true;
    }

    build_combined<<<(KTOT * NOUT + 255) / 256, 256>>>(
        W_proj, b_proj, W_route, b_route, W_noise, b_noise);

    router_main<<<BATCH / RPB, 256, smem_bytes>>>(
        z_n, z_sea, z_trend, noise_z, noise_r, patch_cand, out);
}

// round 7
// speedup vs baseline: 1.3105x; 1.3105x over previous
#include <cuda_runtime.h>
#include <cuda_bf16.h>
#include <cstdint>
#include <math.h>

#define BATCH   131072
#define DIM     256
#define KTOT    1024
#define NOUT    32
#define MTILE   128      // rows per block
#define KC      64       // fp32 K per chunk
#define NCHUNK  16
#define ASTRIDE 144      // bytes per A smem row: 128 data + 16 pad (ldmatrix conflict-free)
#define ALVL    (128 * ASTRIDE)          // 18432 B per bf16 level
#define BCHUNK  12288                    // B-fragment bytes per chunk (4 ksteps x 4 nt x 3 L x 256B)

// Weights pre-baked into exact mma.m16n8k16 B-fragment order:
// u16 index = (((Kstep*4 + ntile)*3 + level)*32 + lane)*4 + reg*2 + half
__device__ uint16_t g_wfrag[64 * 4 * 3 * 32 * 4];   // 192 KB
__device__ float    g_biasC[NOUT];

// ---------------------------------------------------------------------------
__device__ __forceinline__ uint32_t smem_u32(const void* p) {
    uint32_t a;
    asm("{ .reg .u64 t; cvta.to.shared.u64 t, %1; cvt.u32.u64 %0, t; }"
        : "=r"(a) : "l"(p));
    return a;
}
__device__ __forceinline__ void cpa16(uint32_t saddr, const void* g) {
    asm volatile("cp.async.cg.shared.global [%0], [%1], 16;" :: "r"(saddr), "l"(g));
}
#define CP_COMMIT() asm volatile("cp.async.commit_group;" ::: "memory")
#define CP_WAIT0()  asm volatile("cp.async.wait_group 0;"  ::: "memory")

__device__ __forceinline__ uint32_t pack_bf16x2(float hi, float lo) {
    uint32_t r;
    asm("cvt.rn.bf16x2.f32 %0, %1, %2;" : "=r"(r) : "f"(hi), "f"(lo));
    return r;  // low 16 bits = bf16(lo), high = bf16(hi)
}
__device__ __forceinline__ void sts_v2(uint32_t a, uint32_t x, uint32_t y) {
    asm volatile("st.shared.v2.b32 [%0], {%1,%2};" :: "r"(a), "r"(x), "r"(y) : "memory");
}
#define LDSM4(r, addr) \
    asm volatile("ldmatrix.sync.aligned.m8n8.x4.shared.b16 {%0,%1,%2,%3}, [%4];" \
        : "=r"((r)[0]), "=r"((r)[1]), "=r"((r)[2]), "=r"((r)[3]) : "r"(addr))
#define LDS64(r, addr) \
    asm volatile("ld.shared.v2.b32 {%0,%1}, [%2];" \
        : "=r"((r)[0]), "=r"((r)[1]) : "r"(addr))
#define MMA_BF16(c, a, b) \
    asm volatile("mma.sync.aligned.m16n8k16.row.col.f32.bf16.bf16.f32 " \
        "{%0,%1,%2,%3}, {%4,%5,%6,%7}, {%8,%9}, {%0,%1,%2,%3};" \
        : "+f"((c)[0]), "+f"((c)[1]), "+f"((c)[2]), "+f"((c)[3]) \
        : "r"((a)[0]), "r"((a)[1]), "r"((a)[2]), "r"((a)[3]), \
          "r"((b)[0]), "r"((b)[1]))

// ---------------------------------------------------------------------------
// Pre-kernel: combined weights (fp64 accum, coalesced) -> 3-level bf16 split
// written directly in mma B-fragment order.
// ---------------------------------------------------------------------------
__global__ void build_combined(const float* __restrict__ W_proj,
                               const float* __restrict__ b_proj,
                               const float* __restrict__ W_route,
                               const float* __restrict__ b_route,
                               const float* __restrict__ W_noise,
                               const float* __restrict__ b_noise) {
    int idx = blockIdx.x * blockDim.x + threadIdx.x;   // 32768
    if (idx >= NOUT * KTOT) return;
    int o = idx >> 10;          // 0..31 (uniform per warp)
    int k = idx & 1023;         // lane-fast -> coalesced W_proj
    int p = o & 15;
    const float* Wsel = (o < 16) ? W_route : W_noise;

    float val;
    if (k < 768) {
        double a0 = 0.0, a1 = 0.0, a2 = 0.0, a3 = 0.0;
        #pragma unroll 4
        for (int d = 0; d < 256; d += 4) {
            a0 += (double)Wsel[p * 256 + d + 0] * (double)W_proj[(d + 0) * 768 + k];
            a1 += (double)Wsel[p * 256 + d + 1] * (double)W_proj[(d + 1) * 768 + k];
            a2 += (double)Wsel[p * 256 + d + 2] * (double)W_proj[(d + 2) * 768 + k];
            a3 += (double)Wsel[p * 256 + d + 3] * (double)W_proj[(d + 3) * 768 + k];
        }
        val = (float)((a0 + a1) + (a2 + a3));
    } else {
        val = 0.1f * Wsel[p * 256 + (k - 768)];
    }

    __nv_bfloat16 b0 = __float2bfloat16_rn(val);
    float r1 = val - __bfloat162float(b0);
    __nv_bfloat16 b1 = __float2bfloat16_rn(r1);
    float r2 = r1 - __bfloat162float(b1);
    __nv_bfloat16 b2 = __float2bfloat16_rn(r2);

    // fragment coordinates (mma.m16n8k16, B col-major k16 x n8)
    int K    = k >> 4;
    int ko   = k & 15;
    int t    = o >> 3;
    int n    = o & 7;
    int tig  = (ko >> 1) & 3;
    int w    = (ko >> 3) & 1;
    int half = ko & 1;
    int lane = n * 4 + tig;
    int base = (((K * 4 + t) * 3 + 0) * 32 + lane) * 4 + w * 2 + half;
    g_wfrag[base]            = __bfloat16_as_ushort(b0);
    g_wfrag[base + 32 * 4]   = __bfloat16_as_ushort(b1);   // level stride = 32 lanes * 4 u16
    g_wfrag[base + 64 * 4]   = __bfloat16_as_ushort(b2);

    if (k == 0) {
        double a0 = (o < 16) ? (double)b_route[p] : (double)b_noise[p];
        for (int d = 0; d < 256; d++)
            a0 += (double)Wsel[p * 256 + d] * (double)b_proj[d];
        g_biasC[o] = (float)a0;
    }
}

// ---------------------------------------------------------------------------
// Main kernel: emulated-fp32 GEMM [128,1024]x[1024,32] via bf16 3-split on
// mma.sync.m16n8k16, fused softplus/noise/softmax/top4 epilogue.
// Warp tile: 32 rows x 16 outs (2 m16 x 2 n8 tiles). 8 warps.
// ---------------------------------------------------------------------------
__global__ __launch_bounds__(256) void router_mma(
    const float* __restrict__ z_n,     const float* __restrict__ z_sea,
    const float* __restrict__ z_trend, const float* __restrict__ noise_z,
    const float* __restrict__ noise_r, const int* __restrict__ patch_cand,
    float* __restrict__ out)
{
    extern __shared__ char dsm[];
    const uint32_t AS = smem_u32(dsm);          // 3 x 18432 B (bf16 A levels)
    const uint32_t BS = AS + 3 * ALVL;          // 12288 B (B fragments)

    const int tid  = threadIdx.x;
    const int wid  = tid >> 5;
    const int lane = tid & 31;
    const int row0 = blockIdx.x * MTILE;

    // staging coords (same as proven R2/R6 pattern)
    const int sub = (wid << 1) + (lane >> 4);   // 0..15
    const int seg = lane & 15;                  // 16B segment (4 floats)

    // mma coords
    const int Rb  = (wid & 3) * 32;             // warp row base
    const int Nb  = (wid >> 2) * 16;            // warp out base (ntiles Nb/8, Nb/8+1)
    const int gid = lane >> 2, tig = lane & 3;

    float acc0[2][2][4];   // (0,0) product: dominant term
    float acc1[2][2][4];   // cross terms (kept separate for accuracy)
    #pragma unroll
    for (int mt = 0; mt < 2; mt++)
        #pragma unroll
        for (int nt = 0; nt < 2; nt++)
            #pragma unroll
            for (int i = 0; i < 4; i++) { acc0[mt][nt][i] = 0.f; acc1[mt][nt][i] = 0.f; }

    float4 rc[8], rn[8];
    auto ldchunk = [&](float4* r, int c) {
        const float* src = (c < 8) ? ((c < 4) ? z_n : z_sea)
                                   : ((c < 12) ? z_trend : noise_z);
        const float* p = src + (size_t)(row0 + sub) * DIM + (c & 3) * KC + seg * 4;
        #pragma unroll
        for (int g = 0; g < 8; g++)
            r[g] = __ldg((const float4*)(p + (size_t)g * 16 * DIM));
    };

    ldchunk(rc, 0);

    for (int c = 0; c < NCHUNK; c++) {
        if (c + 1 < NCHUNK) ldchunk(rn, c + 1);

        // stage B fragments for this chunk (12 KB, 3 x 16B per thread)
        #pragma unroll
        for (int i = 0; i < 3; i++) {
            int flat = tid + i * 256;           // 0..767
            cpa16(BS + flat * 16, (const char*)g_wfrag + (size_t)c * BCHUNK + flat * 16);
        }
        CP_COMMIT();

        // convert fp32 -> 3-level bf16, STS
        #pragma unroll
        for (int g = 0; g < 8; g++) {
            float4 f = rc[g];
            uint32_t p0 = pack_bf16x2(f.y, f.x);
            uint32_t p1 = pack_bf16x2(f.w, f.z);
            float r0 = f.x - __uint_as_float(p0 << 16);
            float r1 = f.y - __uint_as_float(p0 & 0xFFFF0000u);
            float r2 = f.z - __uint_as_float(p1 << 16);
            float r3 = f.w - __uint_as_float(p1 & 0xFFFF0000u);
            uint32_t q0 = pack_bf16x2(r1, r0);
            uint32_t q1 = pack_bf16x2(r3, r2);
            float s0 = r0 - __uint_as_float(q0 << 16);
            float s1 = r1 - __uint_as_float(q0 & 0xFFFF0000u);
            float s2 = r2 - __uint_as_float(q1 << 16);
            float s3 = r3 - __uint_as_float(q1 & 0xFFFF0000u);
            uint32_t t0 = pack_bf16x2(s1, s0);
            uint32_t t1 = pack_bf16x2(s3, s2);

            uint32_t a = AS + (uint32_t)(g * 16 + sub) * ASTRIDE + seg * 8;
            sts_v2(a,            p0, p1);
            sts_v2(a + ALVL,     q0, q1);
            sts_v2(a + 2 * ALVL, t0, t1);
        }
        CP_WAIT0();
        __syncthreads();

        // compute: 4 k16 steps
        #pragma unroll
        for (int ks = 0; ks < 4; ks++) {
            uint32_t afr[2][3][4];
            const uint32_t arow = (uint32_t)((lane & 7) + ((lane >> 3) & 1) * 8);
            const uint32_t acol = (uint32_t)(ks * 32 + (lane >> 4) * 16);
            #pragma unroll
            for (int mt = 0; mt < 2; mt++)
                #pragma unroll
                for (int L = 0; L < 3; L++)
                    LDSM4(afr[mt][L],
                          AS + L * ALVL + (Rb + mt * 16 + arow) * ASTRIDE + acol);

            uint32_t bfr[2][3][2];
            #pragma unroll
            for (int nt = 0; nt < 2; nt++)
                #pragma unroll
                for (int L = 0; L < 3; L++)
                    LDS64(bfr[nt][L],
                          BS + (uint32_t)((((ks * 4 + (Nb >> 3) + nt) * 3 + L) * 32 + lane) * 8));

            #pragma unroll
            for (int mt = 0; mt < 2; mt++)
                #pragma unroll
                for (int nt = 0; nt < 2; nt++) {
                    MMA_BF16(acc0[mt][nt], afr[mt][0], bfr[nt][0]);  // hi*hi
                    MMA_BF16(acc1[mt][nt], afr[mt][0], bfr[nt][1]);  // hi*mid
                    MMA_BF16(acc1[mt][nt], afr[mt][1], bfr[nt][0]);  // mid*hi
                    MMA_BF16(acc1[mt][nt], afr[mt][1], bfr[nt][1]);  // mid*mid
                    MMA_BF16(acc1[mt][nt], afr[mt][0], bfr[nt][2]);  // hi*lo
                    MMA_BF16(acc1[mt][nt], afr[mt][2], bfr[nt][0]);  // lo*hi
                }
        }
        __syncthreads();
        #pragma unroll
        for (int g = 0; g < 8; g++) rc[g] = rn[g];
    }

    // ---- stash per-row results (overlay A smem; sync above guards reuse) ----
    float (*res)[33] = (float(*)[33])dsm;       // 128 x 33 floats
    #pragma unroll
    for (int mt = 0; mt < 2; mt++)
        #pragma unroll
        for (int nt = 0; nt < 2; nt++) {
            int r = Rb + mt * 16 + gid;
            int cb = Nb + nt * 8 + 2 * tig;
            res[r][cb]         = acc0[mt][nt][0] + acc1[mt][nt][0];
            res[r][cb + 1]     = acc0[mt][nt][1] + acc1[mt][nt][1];
            res[r + 8][cb]     = acc0[mt][nt][2] + acc1[mt][nt][2];
            res[r + 8][cb + 1] = acc0[mt][nt][3] + acc1[mt][nt][3];
        }
    __syncthreads();

    // ---- epilogue: one thread per row (threads 0..127) ----
    if (tid < MTILE) {
        const int grow = row0 + tid;
        float v[32];
        #pragma unroll
        for (int o = 0; o < 32; o++) v[o] = res[tid][o];

        float nr[16];
        #pragma unroll
        for (int i = 0; i < 4; i++) {
            float4 t = __ldg((const float4*)(noise_r + (size_t)grow * 16 + i * 4));
            nr[i*4+0] = t.x; nr[i*4+1] = t.y; nr[i*4+2] = t.z; nr[i*4+3] = t.w;
        }

        float logit[16];
        #pragma unroll
        for (int p = 0; p < 16; p++) {
            float pre = v[16 + p] + g_biasC[16 + p];
            float sp  = fmaxf(pre, 0.0f) + log1pf(expf(-fabsf(pre)));
            logit[p]  = v[p] + g_biasC[p] + nr[p] * sp;
        }
        float m = logit[0];
        #pragma unroll
        for (int p = 1; p < 16; p++) m = fmaxf(m, logit[p]);
        float e[16], s = 0.0f;
        #pragma unroll
        for (int p = 0; p < 16; p++) { e[p] = expf(logit[p] - m); s += e[p]; }
        float w[16];
        #pragma unroll
        for (int p = 0; p < 16; p++) w[p] = e[p] / s;

        float sp_out[16];
        #pragma unroll
        for (int p = 0; p < 16; p++) sp_out[p] = 0.0f;
        int idxs[4];
        unsigned mask = 0u;
        #pragma unroll
        for (int kk = 0; kk < 4; kk++) {
            float best = -1.0f; int bi = 0;
            #pragma unroll
            for (int p = 0; p < 16; p++) {
                bool fr = ((mask >> p) & 1u) == 0u;
                if (fr && w[p] > best) { best = w[p]; bi = p; }
            }
            mask |= 1u << bi;
            idxs[kk] = bi;
            sp_out[bi] = best;
        }

        float* sp_ptr = out + (size_t)grow * 16;
        #pragma unroll
        for (int i = 0; i < 4; i++)
            *(float4*)(sp_ptr + i * 4) = make_float4(sp_out[i*4+0], sp_out[i*4+1],
                                                     sp_out[i*4+2], sp_out[i*4+3]);
        float* pp = out + (size_t)BATCH * 16 + (size_t)grow * 4;
        float* ip = out + (size_t)BATCH * 20 + (size_t)grow * 4;
        #pragma unroll
        for (int kk = 0; kk < 4; kk++) {
            pp[kk] = (float)__ldg(patch_cand + idxs[kk]);
            ip[kk] = (float)idxs[kk];
        }
    }
}

// ---------------------------------------------------------------------------
extern "C" void kernel_launch(void* const* d_in, const int* in_sizes, int n_in,
                              void* d_out, int out_size) {
    const float* z_n        = (const float*)d_in[0];
    const float* z_sea      = (const float*)d_in[1];
    const float* z_trend    = (const float*)d_in[2];
    const float* noise_z    = (const float*)d_in[3];
    const float* noise_r    = (const float*)d_in[4];
    const int*   patch_cand = (const int*)  d_in[5];
    const float* W_proj     = (const float*)d_in[6];
    const float* b_proj     = (const float*)d_in[7];
    const float* W_route    = (const float*)d_in[8];
    const float* b_route    = (const float*)d_in[9];
    const float* W_noise    = (const float*)d_in[10];
    const float* b_noise    = (const float*)d_in[11];
    float* out = (float*)d_out;

    const int smem_bytes = 3 * ALVL + BCHUNK;   // 55296 + 12288 = 67584
    static bool attr_set = false;
    if (!attr_set) {
        cudaFuncSetAttribute(router_mma,
                             cudaFuncAttributeMaxDynamicSharedMemorySize,
                             smem_bytes);
        attr_set = true;
    }

    build_combined<<<(NOUT * KTOT + 255) / 256, 256>>>(
        W_proj, b_proj, W_route, b_route, W_noise, b_noise);

    router_mma<<<BATCH / MTILE, 256, smem_bytes>>>(
        z_n, z_sea, z_trend, noise_z, noise_r, patch_cand, out);
}

// round 8
// speedup vs baseline: 1.7399x; 1.3276x over previous
#include <cuda_runtime.h>
#include <cuda_fp16.h>
#include <cstdint>
#include <math.h>

#define BATCH   131072
#define DIM     256
#define KTOT    1024
#define NOUT    32
#define MTILE   128      // rows per block
#define NCHUNK  16
#define BCHUNK  8192     // B-fragment bytes per chunk: 4ks x 4nt x 32lane x 16B

// Weights pre-baked in PERMUTED mma B-fragment layout, fp16 2-level split,
// scaled by 128 (exact power of 2; epilogue multiplies by 1/128).
// u16 idx = (((chunk*4+ks)*4+nt)*32+lane)*8 + level*4 + reg*2 + half
__device__ uint16_t g_wfrag[NCHUNK * 4 * 4 * 32 * 8];   // 128 KB
__device__ float    g_biasC[NOUT];

// ---------------------------------------------------------------------------
__device__ __forceinline__ uint32_t smem_u32(const void* p) {
    uint32_t a;
    asm("{ .reg .u64 t; cvta.to.shared.u64 t, %1; cvt.u32.u64 %0, t; }"
        : "=r"(a) : "l"(p));
    return a;
}
__device__ __forceinline__ void cpa16(uint32_t saddr, const void* g) {
    asm volatile("cp.async.cg.shared.global [%0], [%1], 16;" :: "r"(saddr), "l"(g));
}
#define CP_COMMIT() asm volatile("cp.async.commit_group;" ::: "memory")
#define CP_WAIT1()  asm volatile("cp.async.wait_group 1;"  ::: "memory")
#define CP_WAIT0()  asm volatile("cp.async.wait_group 0;"  ::: "memory")

// pack two fp32 -> f16x2 (lo -> low half, hi -> high half)
__device__ __forceinline__ uint32_t pack_f16x2(float hi, float lo) {
    uint32_t r;
    asm("cvt.rn.f16x2.f32 %0, %1, %2;" : "=r"(r) : "f"(hi), "f"(lo));
    return r;
}
__device__ __forceinline__ float lo_f16_as_f32(uint32_t h2) {
    float f;
    asm("{ .reg .b16 a, b; mov.b32 {a, b}, %1; cvt.f32.f16 %0, a; }" : "=f"(f) : "r"(h2));
    return f;
}
__device__ __forceinline__ float hi_f16_as_f32(uint32_t h2) {
    float f;
    asm("{ .reg .b16 a, b; mov.b32 {a, b}, %1; cvt.f32.f16 %0, b; }" : "=f"(f) : "r"(h2));
    return f;
}
#define LDS128(r, addr) \
    asm volatile("ld.shared.v4.b32 {%0,%1,%2,%3}, [%4];" \
        : "=r"((r)[0]), "=r"((r)[1]), "=r"((r)[2]), "=r"((r)[3]) : "r"(addr))
#define MMA_F16(c, a0, a1, a2, a3, b0, b1) \
    asm volatile("mma.sync.aligned.m16n8k16.row.col.f32.f16.f16.f32 " \
        "{%0,%1,%2,%3}, {%4,%5,%6,%7}, {%8,%9}, {%0,%1,%2,%3};" \
        : "+f"((c)[0]), "+f"((c)[1]), "+f"((c)[2]), "+f"((c)[3]) \
        : "r"(a0), "r"(a1), "r"(a2), "r"(a3), "r"(b0), "r"(b1))

// ---------------------------------------------------------------------------
// Pre-kernel: fp64 combine -> x128 scale -> fp16 2-level split -> permuted
// B-fragment bake. Permutation: frag-k f = reg*8 + tig*2 + half  <->
// real ko = tig*4 + reg*2 + half  (so A frags come from float4 loads).
// ---------------------------------------------------------------------------
__global__ void build_combined(const float* __restrict__ W_proj,
                               const float* __restrict__ b_proj,
                               const float* __restrict__ W_route,
                               const float* __restrict__ b_route,
                               const float* __restrict__ W_noise,
                               const float* __restrict__ b_noise) {
    int idx = blockIdx.x * blockDim.x + threadIdx.x;   // 32768
    if (idx >= NOUT * KTOT) return;
    int o = idx >> 10;          // 0..31 (uniform per warp)
    int k = idx & 1023;         // lane-fast -> coalesced W_proj
    int p = o & 15;
    const float* Wsel = (o < 16) ? W_route : W_noise;

    float val;
    if (k < 768) {
        double a0 = 0.0, a1 = 0.0, a2 = 0.0, a3 = 0.0;
        #pragma unroll 4
        for (int d = 0; d < 256; d += 4) {
            a0 += (double)Wsel[p * 256 + d + 0] * (double)W_proj[(d + 0) * 768 + k];
            a1 += (double)Wsel[p * 256 + d + 1] * (double)W_proj[(d + 1) * 768 + k];
            a2 += (double)Wsel[p * 256 + d + 2] * (double)W_proj[(d + 2) * 768 + k];
            a3 += (double)Wsel[p * 256 + d + 3] * (double)W_proj[(d + 3) * 768 + k];
        }
        val = (float)((a0 + a1) + (a2 + a3));
    } else {
        val = 0.1f * Wsel[p * 256 + (k - 768)];
    }

    float sv = val * 128.0f;                 // exact scaling, keeps lo normal
    __half h = __float2half_rn(sv);
    __half l = __float2half_rn(sv - __half2float(h));

    int chunk = k >> 6, ks = (k >> 4) & 3, ko = k & 15;
    int tig = ko >> 2, reg = (ko >> 1) & 1, half = ko & 1;
    int nt = o >> 3, n = o & 7;
    int lane = n * 4 + tig;
    int base = (((chunk * 4 + ks) * 4 + nt) * 32 + lane) * 8 + reg * 2 + half;
    g_wfrag[base]     = __half_as_ushort(h);   // level 0 (hi)
    g_wfrag[base + 4] = __half_as_ushort(l);   // level 1 (lo)

    if (k == 0) {
        double a0 = (o < 16) ? (double)b_route[p] : (double)b_noise[p];
        for (int d = 0; d < 256; d++)
            a0 += (double)Wsel[p * 256 + d] * (double)b_proj[d];
        g_biasC[o] = (float)a0;
    }
}

// ---------------------------------------------------------------------------
// Main kernel: emulated-fp32 GEMM [128,1024]x[1024,32] via fp16 2-split on
// mma.sync.m16n8k16 (3 MMAs per tile). A loaded gmem->registers directly in
// fragment layout (permuted k). B double-buffered in smem via cp.async.
// Warp tile: 16 rows x 32 outs. 8 warps. Fused softmax/top4 epilogue.
// ---------------------------------------------------------------------------
__global__ __launch_bounds__(256) void router_mma2(
    const float* __restrict__ z_n,     const float* __restrict__ z_sea,
    const float* __restrict__ z_trend, const float* __restrict__ noise_z,
    const float* __restrict__ noise_r, const int* __restrict__ patch_cand,
    float* __restrict__ out)
{
    extern __shared__ char dsm[];
    const uint32_t BS = smem_u32(dsm);          // 2 x 8192 B (B fragments)
    float (*res)[33] = (float(*)[33])(dsm + 2 * BCHUNK);   // 128 x 33 fp32

    const int tid  = threadIdx.x;
    const int wid  = tid >> 5;
    const int lane = tid & 31;
    const int row0 = blockIdx.x * MTILE;
    const int gid  = lane >> 2, tig = lane & 3;
    const int rA   = row0 + wid * 16 + gid;     // global row for a0/a2

    // A loader: per ks, float4 at (rA, colbase + ks*16 + tig*4) and (rA+8, ...)
    auto lda = [&](float4* r, int c) {
        const float* src = (c < 8) ? ((c < 4) ? z_n : z_sea)
                                   : ((c < 12) ? z_trend : noise_z);
        const float* p0 = src + (size_t)rA * DIM + (c & 3) * 64 + tig * 4;
        #pragma unroll
        for (int ks = 0; ks < 4; ks++) {
            r[2 * ks]     = __ldg((const float4*)(p0 + ks * 16));
            r[2 * ks + 1] = __ldg((const float4*)(p0 + 8 * DIM + ks * 16));
        }
    };
    auto stageB = [&](int buf, int c) {
        uint32_t dst = BS + buf * BCHUNK + tid * 32;
        const char* src = (const char*)g_wfrag + (size_t)c * BCHUNK + tid * 32;
        cpa16(dst, src);
        cpa16(dst + 16, src + 16);
    };

    float acc0[4][4], acc1[4][4];
    #pragma unroll
    for (int nt = 0; nt < 4; nt++)
        #pragma unroll
        for (int i = 0; i < 4; i++) { acc0[nt][i] = 0.f; acc1[nt][i] = 0.f; }

    float4 rc[8], rn[8];
    stageB(0, 0);
    CP_COMMIT();
    lda(rc, 0);

    for (int c = 0; c < NCHUNK; c++) {
        if (c + 1 < NCHUNK) {
            lda(rn, c + 1);
            stageB((c + 1) & 1, c + 1);
            CP_COMMIT();
            CP_WAIT1();
        } else {
            CP_WAIT0();
        }
        __syncthreads();                        // B(c) visible to all warps

        const uint32_t bb = BS + (c & 1) * BCHUNK;
        #pragma unroll
        for (int ks = 0; ks < 4; ks++) {
            float4 v0 = rc[2 * ks], v1 = rc[2 * ks + 1];
            // hi level (frag regs: a0=v0.xy a1=v1.xy a2=v0.zw a3=v1.zw)
            uint32_t h0 = pack_f16x2(v0.y, v0.x);
            uint32_t h1 = pack_f16x2(v1.y, v1.x);
            uint32_t h2 = pack_f16x2(v0.w, v0.z);
            uint32_t h3 = pack_f16x2(v1.w, v1.z);
            // lo level = exact residual
            uint32_t l0 = pack_f16x2(v0.y - hi_f16_as_f32(h0), v0.x - lo_f16_as_f32(h0));
            uint32_t l1 = pack_f16x2(v1.y - hi_f16_as_f32(h1), v1.x - lo_f16_as_f32(h1));
            uint32_t l2 = pack_f16x2(v0.w - hi_f16_as_f32(h2), v0.z - lo_f16_as_f32(h2));
            uint32_t l3 = pack_f16x2(v1.w - hi_f16_as_f32(h3), v1.z - lo_f16_as_f32(h3));

            #pragma unroll
            for (int nt = 0; nt < 4; nt++) {
                uint32_t b[4];
                LDS128(b, bb + (uint32_t)(((ks * 4 + nt) * 32 + lane) * 16));
                MMA_F16(acc0[nt], h0, h1, h2, h3, b[0], b[1]);  // hi*hi
                MMA_F16(acc1[nt], h0, h1, h2, h3, b[2], b[3]);  // hi*lo
                MMA_F16(acc1[nt], l0, l1, l2, l3, b[0], b[1]);  // lo*hi
            }
        }
        __syncthreads();                        // all reads of buf done
        #pragma unroll
        for (int g = 0; g < 8; g++) rc[g] = rn[g];
    }

    // ---- stash per-row results (undo x128 weight scale) ----
    #pragma unroll
    for (int nt = 0; nt < 4; nt++) {
        int cb = nt * 8 + tig * 2;
        int r  = wid * 16 + gid;
        res[r][cb]         = (acc0[nt][0] + acc1[nt][0]) * 0.0078125f;
        res[r][cb + 1]     = (acc0[nt][1] + acc1[nt][1]) * 0.0078125f;
        res[r + 8][cb]     = (acc0[nt][2] + acc1[nt][2]) * 0.0078125f;
        res[r + 8][cb + 1] = (acc0[nt][3] + acc1[nt][3]) * 0.0078125f;
    }
    __syncthreads();

    // ---- epilogue: one thread per row (threads 0..127) ----
    if (tid < MTILE) {
        const int grow = row0 + tid;
        float v[32];
        #pragma unroll
        for (int o = 0; o < 32; o++) v[o] = res[tid][o];

        float nr[16];
        #pragma unroll
        for (int i = 0; i < 4; i++) {
            float4 t = __ldg((const float4*)(noise_r + (size_t)grow * 16 + i * 4));
            nr[i*4+0] = t.x; nr[i*4+1] = t.y; nr[i*4+2] = t.z; nr[i*4+3] = t.w;
        }

        float logit[16];
        #pragma unroll
        for (int p = 0; p < 16; p++) {
            float pre = v[16 + p] + g_biasC[16 + p];
            float sp  = fmaxf(pre, 0.0f) + log1pf(expf(-fabsf(pre)));
            logit[p]  = v[p] + g_biasC[p] + nr[p] * sp;
        }
        float m = logit[0];
        #pragma unroll
        for (int p = 1; p < 16; p++) m = fmaxf(m, logit[p]);
        float e[16], s = 0.0f;
        #pragma unroll
        for (int p = 0; p < 16; p++) { e[p] = expf(logit[p] - m); s += e[p]; }
        float w[16];
        #pragma unroll
        for (int p = 0; p < 16; p++) w[p] = e[p] / s;

        float sp_out[16];
        #pragma unroll
        for (int p = 0; p < 16; p++) sp_out[p] = 0.0f;
        int idxs[4];
        unsigned mask = 0u;
        #pragma unroll
        for (int kk = 0; kk < 4; kk++) {
            float best = -1.0f; int bi = 0;
            #pragma unroll
            for (int p = 0; p < 16; p++) {
                bool fr = ((mask >> p) & 1u) == 0u;
                if (fr && w[p] > best) { best = w[p]; bi = p; }
            }
            mask |= 1u << bi;
            idxs[kk] = bi;
            sp_out[bi] = best;
        }

        float* sp_ptr = out + (size_t)grow * 16;
        #pragma unroll
        for (int i = 0; i < 4; i++)
            *(float4*)(sp_ptr + i * 4) = make_float4(sp_out[i*4+0], sp_out[i*4+1],
                                                     sp_out[i*4+2], sp_out[i*4+3]);
        float* pp = out + (size_t)BATCH * 16 + (size_t)grow * 4;
        float* ip = out + (size_t)BATCH * 20 + (size_t)grow * 4;
        #pragma unroll
        for (int kk = 0; kk < 4; kk++) {
            pp[kk] = (float)__ldg(patch_cand + idxs[kk]);
            ip[kk] = (float)idxs[kk];
        }
    }
}

// ---------------------------------------------------------------------------
extern "C" void kernel_launch(void* const* d_in, const int* in_sizes, int n_in,
                              void* d_out, int out_size) {
    const float* z_n        = (const float*)d_in[0];
    const float* z_sea      = (const float*)d_in[1];
    const float* z_trend    = (const float*)d_in[2];
    const float* noise_z    = (const float*)d_in[3];
    const float* noise_r    = (const float*)d_in[4];
    const int*   patch_cand = (const int*)  d_in[5];
    const float* W_proj     = (const float*)d_in[6];
    const float* b_proj     = (const float*)d_in[7];
    const float* W_route    = (const float*)d_in[8];
    const float* b_route    = (const float*)d_in[9];
    const float* W_noise    = (const float*)d_in[10];
    const float* b_noise    = (const float*)d_in[11];
    float* out = (float*)d_out;

    const int smem_bytes = 2 * BCHUNK + 128 * 33 * 4;   // 16384 + 16896 = 33280
    static bool attr_set = false;
    if (!attr_set) {
        cudaFuncSetAttribute(router_mma2,
                             cudaFuncAttributeMaxDynamicSharedMemorySize,
                             smem_bytes);
        attr_set = true;
    }

    build_combined<<<(NOUT * KTOT + 255) / 256, 256>>>(
        W_proj, b_proj, W_route, b_route, W_noise, b_noise);

    router_mma2<<<BATCH / MTILE, 256, smem_bytes>>>(
        z_n, z_sea, z_trend, noise_z, noise_r, patch_cand, out);
}

// round 10
// speedup vs baseline: 2.2468x; 1.2914x over previous
#include <cuda_runtime.h>
#include <cuda_fp16.h>
#include <cstdint>
#include <math.h>

#define BATCH   131072
#define DIM     256
#define KTOT    1024
#define NOUT    32
#define MTILE   128      // rows per block
#define NCHUNK  16
#define BCHUNK  8192     // B-fragment bytes per chunk: 4ks x 4nt x 32lane x 16B
#define NBUF    3        // B smem buffers; prefetch distance = NBUF-1 = 2

// Weights pre-baked in PERMUTED mma B-fragment layout, fp16 2-level split,
// scaled by 128 (exact power of 2; epilogue multiplies by 1/128).
// u16 idx = (((chunk*4+ks)*4+nt)*32+lane)*8 + level*4 + reg*2 + half
__device__ uint16_t g_wfrag[NCHUNK * 4 * 4 * 32 * 8];   // 128 KB
__device__ float    g_biasC[NOUT];

// ---------------------------------------------------------------------------
__device__ __forceinline__ uint32_t smem_u32(const void* p) {
    uint32_t a;
    asm("{ .reg .u64 t; cvta.to.shared.u64 t, %1; cvt.u32.u64 %0, t; }"
        : "=r"(a) : "l"(p));
    return a;
}
__device__ __forceinline__ void cpa16(uint32_t saddr, const void* g) {
    asm volatile("cp.async.cg.shared.global [%0], [%1], 16;" :: "r"(saddr), "l"(g));
}
#define CP_COMMIT() asm volatile("cp.async.commit_group;" ::: "memory")
#define CP_WAIT2()  asm volatile("cp.async.wait_group 2;"  ::: "memory")
#define CP_WAIT0()  asm volatile("cp.async.wait_group 0;"  ::: "memory")

// pack two fp32 -> f16x2 (lo -> low half, hi -> high half)
__device__ __forceinline__ uint32_t pack_f16x2(float hi, float lo) {
    uint32_t r;
    asm("cvt.rn.f16x2.f32 %0, %1, %2;" : "=r"(r) : "f"(hi), "f"(lo));
    return r;
}
__device__ __forceinline__ float lo_f16_as_f32(uint32_t h2) {
    float f;
    asm("{ .reg .b16 a, b; mov.b32 {a, b}, %1; cvt.f32.f16 %0, a; }" : "=f"(f) : "r"(h2));
    return f;
}
__device__ __forceinline__ float hi_f16_as_f32(uint32_t h2) {
    float f;
    asm("{ .reg .b16 a, b; mov.b32 {a, b}, %1; cvt.f32.f16 %0, b; }" : "=f"(f) : "r"(h2));
    return f;
}
#define LDS128(r, addr) \
    asm volatile("ld.shared.v4.b32 {%0,%1,%2,%3}, [%4];" \
        : "=r"((r)[0]), "=r"((r)[1]), "=r"((r)[2]), "=r"((r)[3]) : "r"(addr))
#define MMA_F16(c, a0, a1, a2, a3, b0, b1) \
    asm volatile("mma.sync.aligned.m16n8k16.row.col.f32.f16.f16.f32 " \
        "{%0,%1,%2,%3}, {%4,%5,%6,%7}, {%8,%9}, {%0,%1,%2,%3};" \
        : "+f"((c)[0]), "+f"((c)[1]), "+f"((c)[2]), "+f"((c)[3]) \
        : "r"(a0), "r"(a1), "r"(a2), "r"(a3), "r"(b0), "r"(b1))

// Compensated accumulate: (s,e) += a*b, error ~2^-45 relative
__device__ __forceinline__ void acc2(float& s, float& e, float a, float b) {
    float p    = a * b;
    float perr = fmaf(a, b, -p);          // exact product error
    float t    = s + p;                   // Knuth 2Sum (branch-free)
    float z    = t - s;
    float serr = (s - (t - z)) + (p - z);
    s = t;
    e += serr + perr;
}

// ---------------------------------------------------------------------------
// Pre-kernel: fp32-compensated combine -> x128 scale -> fp16 2-level split ->
// permuted B-fragment bake. Permutation: frag-k f = reg*8 + tig*2 + half <->
// real ko = tig*4 + reg*2 + half  (so A frags come from float4 loads).
// ---------------------------------------------------------------------------
__global__ void build_combined(const float* __restrict__ W_proj,
                               const float* __restrict__ b_proj,
                               const float* __restrict__ W_route,
                               const float* __restrict__ b_route,
                               const float* __restrict__ W_noise,
                               const float* __restrict__ b_noise) {
    int idx = blockIdx.x * blockDim.x + threadIdx.x;   // 32768
    if (idx >= NOUT * KTOT) return;
    int o = idx >> 10;          // 0..31 (uniform per warp)
    int k = idx & 1023;         // lane-fast -> coalesced W_proj
    int p = o & 15;
    const float* Wsel = (o < 16) ? W_route : W_noise;

    float val;
    if (k < 768) {
        float s0 = 0.f, e0 = 0.f, s1 = 0.f, e1 = 0.f;
        #pragma unroll 4
        for (int d = 0; d < 256; d += 2) {
            acc2(s0, e0, Wsel[p * 256 + d],     W_proj[(d) * 768 + k]);
            acc2(s1, e1, Wsel[p * 256 + d + 1], W_proj[(d + 1) * 768 + k]);
        }
        val = (float)(((double)s0 + (double)s1) + ((double)e0 + (double)e1));
    } else {
        val = 0.1f * Wsel[p * 256 + (k - 768)];
    }

    float sv = val * 128.0f;                 // exact scaling, keeps lo normal
    __half h = __float2half_rn(sv);
    __half l = __float2half_rn(sv - __half2float(h));

    int chunk = k >> 6, ks = (k >> 4) & 3, ko = k & 15;
    int tig = ko >> 2, reg = (ko >> 1) & 1, half = ko & 1;
    int nt = o >> 3, n = o & 7;
    int lane = n * 4 + tig;
    int base = (((chunk * 4 + ks) * 4 + nt) * 32 + lane) * 8 + reg * 2 + half;
    g_wfrag[base]     = __half_as_ushort(h);   // level 0 (hi)
    g_wfrag[base + 4] = __half_as_ushort(l);   // level 1 (lo)

    if (k == 0) {
        float s0 = 0.f, e0 = 0.f;
        for (int d = 0; d < 256; d++)
            acc2(s0, e0, Wsel[p * 256 + d], b_proj[d]);
        float bsel = (o < 16) ? b_route[p] : b_noise[p];
        g_biasC[o] = (float)((double)bsel + (double)s0 + (double)e0);
    }
}

// ---------------------------------------------------------------------------
// Main kernel: emulated-fp32 GEMM [128,1024]x[1024,32] via fp16 2-split on
// mma.sync.m16n8k16 (3 MMAs per tile). A loaded gmem->registers directly in
// fragment layout (permuted k). B triple-buffered in smem via cp.async,
// prefetch distance 2 (buffers: read c%3, in-flight (c+1)%3 and (c+2)%3).
// Warp tile: 16 rows x 32 outs. 8 warps. Fused softmax/top4 epilogue.
// ---------------------------------------------------------------------------
__global__ __launch_bounds__(256) void router_mma2(
    const float* __restrict__ z_n,     const float* __restrict__ z_sea,
    const float* __restrict__ z_trend, const float* __restrict__ noise_z,
    const float* __restrict__ noise_r, const int* __restrict__ patch_cand,
    float* __restrict__ out)
{
    extern __shared__ char dsm[];
    const uint32_t BS = smem_u32(dsm);          // NBUF x 8192 B (B fragments)
    float (*res)[33] = (float(*)[33])(dsm + NBUF * BCHUNK);   // 128 x 33 fp32

    const int tid  = threadIdx.x;
    const int wid  = tid >> 5;
    const int lane = tid & 31;
    const int row0 = blockIdx.x * MTILE;
    const int gid  = lane >> 2, tig = lane & 3;
    const int rA   = row0 + wid * 16 + gid;     // global row for a0/a2

    // A loader: per ks, float4 at (rA, colbase + ks*16 + tig*4) and (rA+8, ...)
    auto lda = [&](float4* r, int c) {
        const float* src = (c < 8) ? ((c < 4) ? z_n : z_sea)
                                   : ((c < 12) ? z_trend : noise_z);
        const float* p0 = src + (size_t)rA * DIM + (c & 3) * 64 + tig * 4;
        #pragma unroll
        for (int ks = 0; ks < 4; ks++) {
            r[2 * ks]     = __ldg((const float4*)(p0 + ks * 16));
            r[2 * ks + 1] = __ldg((const float4*)(p0 + 8 * DIM + ks * 16));
        }
    };
    auto stageB = [&](int c) {
        uint32_t dst = BS + (c % NBUF) * BCHUNK + tid * 32;
        const char* src = (const char*)g_wfrag + (size_t)c * BCHUNK + tid * 32;
        cpa16(dst, src);
        cpa16(dst + 16, src + 16);
        CP_COMMIT();
    };

    float acc0[4][4], acc1[4][4];
    #pragma unroll
    for (int nt = 0; nt < 4; nt++)
        #pragma unroll
        for (int i = 0; i < 4; i++) { acc0[nt][i] = 0.f; acc1[nt][i] = 0.f; }

    float4 rc[8], rn[8];
    stageB(0);          // group 0
    stageB(1);          // group 1
    lda(rc, 0);

    for (int c = 0; c < NCHUNK; c++) {
        if (c + 1 < NCHUNK) lda(rn, c + 1);
        if (c + 2 < NCHUNK) { stageB(c + 2); CP_WAIT2(); }  // group c lands
        else                { CP_WAIT0(); }
        __syncthreads();                        // B(c) visible to all warps

        const uint32_t bb = BS + (c % NBUF) * BCHUNK;
        #pragma unroll
        for (int ks = 0; ks < 4; ks++) {
            float4 v0 = rc[2 * ks], v1 = rc[2 * ks + 1];
            // hi level (frag regs: a0=v0.xy a1=v1.xy a2=v0.zw a3=v1.zw)
            uint32_t h0 = pack_f16x2(v0.y, v0.x);
            uint32_t h1 = pack_f16x2(v1.y, v1.x);
            uint32_t h2 = pack_f16x2(v0.w, v0.z);
            uint32_t h3 = pack_f16x2(v1.w, v1.z);
            // lo level = exact residual
            uint32_t l0 = pack_f16x2(v0.y - hi_f16_as_f32(h0), v0.x - lo_f16_as_f32(h0));
            uint32_t l1 = pack_f16x2(v1.y - hi_f16_as_f32(h1), v1.x - lo_f16_as_f32(h1));
            uint32_t l2 = pack_f16x2(v0.w - hi_f16_as_f32(h2), v0.z - lo_f16_as_f32(h2));
            uint32_t l3 = pack_f16x2(v1.w - hi_f16_as_f32(h3), v1.z - lo_f16_as_f32(h3));

            #pragma unroll
            for (int nt = 0; nt < 4; nt++) {
                uint32_t b[4];
                LDS128(b, bb + (uint32_t)(((ks * 4 + nt) * 32 + lane) * 16));
                MMA_F16(acc0[nt], h0, h1, h2, h3, b[0], b[1]);  // hi*hi
                MMA_F16(acc1[nt], h0, h1, h2, h3, b[2], b[3]);  // hi*lo
                MMA_F16(acc1[nt], l0, l1, l2, l3, b[0], b[1]);  // lo*hi
            }
        }
        __syncthreads();                        // all reads of this buf done
        #pragma unroll
        for (int g = 0; g < 8; g++) rc[g] = rn[g];
    }

    // ---- stash per-row results (undo x128 weight scale) ----
    #pragma unroll
    for (int nt = 0; nt < 4; nt++) {
        int cb = nt * 8 + tig * 2;
        int r  = wid * 16 + gid;
        res[r][cb]         = (acc0[nt][0] + acc1[nt][0]) * 0.0078125f;
        res[r][cb + 1]     = (acc0[nt][1] + acc1[nt][1]) * 0.0078125f;
        res[r + 8][cb]     = (acc0[nt][2] + acc1[nt][2]) * 0.0078125f;
        res[r + 8][cb + 1] = (acc0[nt][3] + acc1[nt][3]) * 0.0078125f;
    }
    __syncthreads();

    // ---- epilogue: one thread per row (threads 0..127) ----
    if (tid < MTILE) {
        const int grow = row0 + tid;
        float v[32];
        #pragma unroll
        for (int o = 0; o < 32; o++) v[o] = res[tid][o];

        float nr[16];
        #pragma unroll
        for (int i = 0; i < 4; i++) {
            float4 t = __ldg((const float4*)(noise_r + (size_t)grow * 16 + i * 4));
            nr[i*4+0] = t.x; nr[i*4+1] = t.y; nr[i*4+2] = t.z; nr[i*4+3] = t.w;
        }

        float logit[16];
        #pragma unroll
        for (int p = 0; p < 16; p++) {
            float pre = v[16 + p] + g_biasC[16 + p];
            float sp  = fmaxf(pre, 0.0f) + log1pf(expf(-fabsf(pre)));
            logit[p]  = v[p] + g_biasC[p] + nr[p] * sp;
        }
        float m = logit[0];
        #pragma unroll
        for (int p = 1; p < 16; p++) m = fmaxf(m, logit[p]);
        float e[16], s = 0.0f;
        #pragma unroll
        for (int p = 0; p < 16; p++) { e[p] = expf(logit[p] - m); s += e[p]; }
        float w[16];
        #pragma unroll
        for (int p = 0; p < 16; p++) w[p] = e[p] / s;

        float sp_out[16];
        #pragma unroll
        for (int p = 0; p < 16; p++) sp_out[p] = 0.0f;
        int idxs[4];
        unsigned mask = 0u;
        #pragma unroll
        for (int kk = 0; kk < 4; kk++) {
            float best = -1.0f; int bi = 0;
            #pragma unroll
            for (int p = 0; p < 16; p++) {
                bool fr = ((mask >> p) & 1u) == 0u;
                if (fr && w[p] > best) { best = w[p]; bi = p; }
            }
            mask |= 1u << bi;
            idxs[kk] = bi;
            sp_out[bi] = best;
        }

        float* sp_ptr = out + (size_t)grow * 16;
        #pragma unroll
        for (int i = 0; i < 4; i++)
            *(float4*)(sp_ptr + i * 4) = make_float4(sp_out[i*4+0], sp_out[i*4+1],
                                                     sp_out[i*4+2], sp_out[i*4+3]);
        float* pp = out + (size_t)BATCH * 16 + (size_t)grow * 4;
        float* ip = out + (size_t)BATCH * 20 + (size_t)grow * 4;
        #pragma unroll
        for (int kk = 0; kk < 4; kk++) {
            pp[kk] = (float)__ldg(patch_cand + idxs[kk]);
            ip[kk] = (float)idxs[kk];
        }
    }
}

// ---------------------------------------------------------------------------
extern "C" void kernel_launch(void* const* d_in, const int* in_sizes, int n_in,
                              void* d_out, int out_size) {
    const float* z_n        = (const float*)d_in[0];
    const float* z_sea      = (const float*)d_in[1];
    const float* z_trend    = (const float*)d_in[2];
    const float* noise_z    = (const float*)d_in[3];
    const float* noise_r    = (const float*)d_in[4];
    const int*   patch_cand = (const int*)  d_in[5];
    const float* W_proj     = (const float*)d_in[6];
    const float* b_proj     = (const float*)d_in[7];
    const float* W_route    = (const float*)d_in[8];
    const float* b_route    = (const float*)d_in[9];
    const float* W_noise    = (const float*)d_in[10];
    const float* b_noise    = (const float*)d_in[11];
    float* out = (float*)d_out;

    const int smem_bytes = NBUF * BCHUNK + 128 * 33 * 4;   // 24576 + 16896 = 41472
    static bool attr_set = false;
    if (!attr_set) {
        cudaFuncSetAttribute(router_mma2,
                             cudaFuncAttributeMaxDynamicSharedMemorySize,
                             smem_bytes);
        attr_set = true;
    }

    build_combined<<<(NOUT * KTOT + 255) / 256, 256>>>(
        W_proj, b_proj, W_route, b_route, W_noise, b_noise);

    router_mma2<<<BATCH / MTILE, 256, smem_bytes>>>(
        z_n, z_sea, z_trend, noise_z, noise_r, patch_cand, out);
}